// round 7
// baseline (speedup 1.0000x reference)
#include <cuda_runtime.h>
#include <cstdint>

#define N_NODES 20000
#define N_EDGES 100000
#define DIM 768
#define NUM_REL 4
#define NBINS (NUM_REL*N_NODES)      // 80000
#define K5  (5*DIM)                  // 3840
#define KA2 (2*K5)                   // 7680 physical cols [q1 | q0]
#define BKT 64
#define NKT 180                      // 60 (hi*hi) + 120 (cross)
#define BM 128
#define BN 128
#define NTHR 512
#define NST 4
#define SROW 80                      // smem row stride (64 int8 + 16 pad)
#define STAGE_A (BM*SROW)            // 10240
#define STAGE_B (BN*SROW)            // 10240
#define STAGE_BYTES (STAGE_A+STAGE_B)// 20480
#define SMEM_DYN (NST*STAGE_BYTES)   // 81920
#define QMAXF 16256.0f

// ---------------- scratch -----------------------------------------------------
__device__ float g_x0[(size_t)N_NODES*DIM];
__device__ float g_x1[(size_t)N_NODES*DIM];
__device__ int8_t g_A8[(size_t)N_NODES*KA2];   // [N][7680]: [a1|a0] K-major
__device__ int8_t g_B8[(size_t)DIM*KA2];       // [768][7680]: [b1|b0] K-major (n-major rows)
__device__ float g_sA[N_NODES];
__device__ float g_sB[DIM];
__device__ int g_deg[NBINS];
__device__ int g_ptr[NBINS+1];
__device__ int g_cursor[NBINS];
__device__ int g_esrc[N_EDGES];

// ---------------- helpers -----------------------------------------------------
__device__ __forceinline__ uint32_t sptr(const void* p) {
    return (uint32_t)__cvta_generic_to_shared(p);
}
__device__ __forceinline__ void cpa16(uint32_t s, const void* g, int sz) {
    asm volatile("cp.async.cg.shared.global [%0], [%1], 16, %2;\n"
                 :: "r"(s), "l"(g), "r"(sz));
}
__device__ __forceinline__ const float* pick_x(const float* ext, int sel) {
    return sel == 0 ? g_x0 : (sel == 1 ? g_x1 : ext);
}
__device__ __forceinline__ void quant15(float v, float inv, int8_t& q1, int8_t& q0) {
    int q = __float2int_rn(v * inv);
    q = max(-16256, min(16256, q));
    int h = __float2int_rn((float)q * 0.0078125f);   // q/128, |h|<=127
    q1 = (int8_t)h;
    q0 = (int8_t)(q - (h << 7));                     // |q0|<=64
}

// ---------------- prep: zero+deg+scan in ONE single-block kernel ---------------
__global__ __launch_bounds__(1024) void k_prep(const int* __restrict__ ei,
                                               const int* __restrict__ et) {
    __shared__ int buf[1024];
    __shared__ int carry;
    int tid = threadIdx.x;
    for (int i = tid; i < NBINS; i += 1024) g_deg[i] = 0;
    __syncthreads();
    for (int e = tid; e < N_EDGES; e += 1024)
        atomicAdd(&g_deg[et[e] * N_NODES + ei[N_EDGES + e]], 1);
    __syncthreads();
    if (tid == 0) { carry = 0; g_ptr[0] = 0; }
    __syncthreads();
    for (int base = 0; base < NBINS; base += 1024) {
        int idx = base + tid;
        int v = (idx < NBINS) ? g_deg[idx] : 0;
        buf[tid] = v;
        __syncthreads();
#pragma unroll
        for (int off = 1; off < 1024; off <<= 1) {
            int t = (tid >= off) ? buf[tid - off] : 0;
            __syncthreads();
            buf[tid] += t;
            __syncthreads();
        }
        if (idx < NBINS) {
            int p = carry + buf[tid];
            g_ptr[idx + 1] = p;
            g_cursor[idx]  = p - v;
        }
        __syncthreads();
        if (tid == 0) carry += buf[1023];
        __syncthreads();
    }
}
__global__ void k_place(const int* __restrict__ ei, const int* __restrict__ et) {
    int e = blockIdx.x * blockDim.x + threadIdx.x;
    if (e < N_EDGES) {
        int b = et[e] * N_NODES + ei[N_EDGES + e];
        int pos = atomicAdd(&g_cursor[b], 1);
        g_esrc[pos] = ei[e];
    }
}

// ---------------- fused: aggregate+quantize A  AND  quantize B ----------------
__global__ __launch_bounds__(256) void k_aggconv(const float* __restrict__ x_ext, int xsel,
                                                 const float* __restrict__ root,
                                                 const float* __restrict__ W) {
    __shared__ float rbuf[256];
    int tid = threadIdx.x;
    int b = blockIdx.x;

    if (b < N_NODES) {
        const float* x = pick_x(x_ext, xsel);
        int i = b;
        int c0 = tid * 3;
        float v[5][3];
        {
            const float* xp = x + (size_t)i * DIM + c0;
            v[0][0] = xp[0]; v[0][1] = xp[1]; v[0][2] = xp[2];
        }
#pragma unroll
        for (int r = 0; r < NUM_REL; r++) {
            int bb = r * N_NODES + i;
            int s = g_ptr[bb], e = g_ptr[bb + 1];
            float a0 = 0.f, a1 = 0.f, a2 = 0.f;
            for (int j = s; j < e; j++) {
                const float* q = x + (size_t)g_esrc[j] * DIM + c0;
                a0 += q[0]; a1 += q[1]; a2 += q[2];
            }
            float w = (e > s) ? 1.0f / (float)(e - s) : 0.0f;
            v[r + 1][0] = a0 * w; v[r + 1][1] = a1 * w; v[r + 1][2] = a2 * w;
        }
        float m = 0.f;
#pragma unroll
        for (int s = 0; s < 5; s++)
#pragma unroll
            for (int j = 0; j < 3; j++) m = fmaxf(m, fabsf(v[s][j]));
        rbuf[tid] = m;
        __syncthreads();
        for (int o = 128; o > 0; o >>= 1) {
            if (tid < o) rbuf[tid] = fmaxf(rbuf[tid], rbuf[tid + o]);
            __syncthreads();
        }
        m = rbuf[0];
        float inv = (m > 0.f) ? QMAXF / m : 0.f;
        if (tid == 0) g_sA[i] = m * (1.0f / QMAXF);
        int8_t* rowp = g_A8 + (size_t)i * KA2;
#pragma unroll
        for (int s = 0; s < 5; s++) {
            int col = s * DIM + c0;
#pragma unroll
            for (int j = 0; j < 3; j++) {
                int8_t q1, q0;
                quant15(v[s][j], inv, q1, q0);
                rowp[col + j]      = q1;
                rowp[K5 + col + j] = q0;
            }
        }
    } else {
        int n = b - N_NODES;
        float vals[15];
        float m = 0.f;
#pragma unroll
        for (int t = 0; t < 15; t++) {
            int k = tid + t * 256;
            float a = (k < DIM) ? root[(size_t)k * DIM + n]
                                : W[(size_t)(k - DIM) * DIM + n];
            vals[t] = a;
            m = fmaxf(m, fabsf(a));
        }
        rbuf[tid] = m;
        __syncthreads();
        for (int o = 128; o > 0; o >>= 1) {
            if (tid < o) rbuf[tid] = fmaxf(rbuf[tid], rbuf[tid + o]);
            __syncthreads();
        }
        m = rbuf[0];
        float inv = (m > 0.f) ? QMAXF / m : 0.f;
        if (tid == 0) g_sB[n] = m * (1.0f / QMAXF);
        int8_t* rowp = g_B8 + (size_t)n * KA2;
#pragma unroll
        for (int t = 0; t < 15; t++) {
            int k = tid + t * 256;
            int8_t q1, q0;
            quant15(vals[t], inv, q1, q0);
            rowp[k]      = q1;
            rowp[K5 + k] = q0;
        }
    }
}

// ---------------- int8 IMMA GEMM (512 thr, 4x4 warps, warp tile 32x32) --------
__global__ __launch_bounds__(NTHR) void k_gemm(const float* __restrict__ bias,
                                               float* __restrict__ dout, int outsel,
                                               int relu) {
    extern __shared__ char dsm[];
    float* C = outsel == 0 ? g_x0 : (outsel == 1 ? g_x1 : dout);

    const int tid = threadIdx.x, lane = tid & 31, warp = tid >> 5;
    const int wm = warp >> 2, wn = warp & 3;          // 4x4 warps, tile 32x32
    const int ntile = blockIdx.x, mtile = blockIdx.y;
    const int m_base = mtile * BM, n_base = ntile * BN;

    int acc11[2][4][4], accX[2][4][4];
#pragma unroll
    for (int a = 0; a < 2; a++)
#pragma unroll
        for (int b = 0; b < 4; b++)
#pragma unroll
            for (int c = 0; c < 4; c++) { acc11[a][b][c] = 0; accX[a][b][c] = 0; }

    auto load_tile = [&](int kt, int s) {
        int kA, kB;
        if (kt < 60) { kA = kt * BKT; kB = kt * BKT; }               // A1 x B1
        else {
            int k2 = kt - 60;                                        // cross pass
            kA = k2 * BKT;                                           // [A1|A0]
            kB = (k2 < 60) ? K5 + k2 * BKT : (k2 - 60) * BKT;        // [B0;B1]
        }
        uint32_t as = sptr(dsm + s * STAGE_BYTES);
        uint32_t bs2 = as + STAGE_A;
        {   // A: 512 chunks of 16B, exactly one per thread
            int row = tid >> 2, kc = tid & 3;
            int grow = m_base + row;
            int ok = grow < N_NODES;
            const int8_t* src = g_A8 + (size_t)(ok ? grow : 0) * KA2 + kA + kc * 16;
            cpa16(as + row * SROW + kc * 16, src, ok ? 16 : 0);
        }
        {   // B: 512 chunks of 16B
            int row = tid >> 2, kc = tid & 3;
            const int8_t* src = g_B8 + (size_t)(n_base + row) * KA2 + kB + kc * 16;
            cpa16(bs2 + row * SROW + kc * 16, src, 16);
        }
        asm volatile("cp.async.commit_group;\n");
    };

    auto compute = [&](int s, int (&acc)[2][4][4]) {
        char* As = dsm + s * STAGE_BYTES;
        char* Bs = As + STAGE_A;
#pragma unroll
        for (int ks = 0; ks < BKT; ks += 32) {
            uint32_t af[2][4];
#pragma unroll
            for (int mi = 0; mi < 2; mi++) {
                int rr = wm * 32 + mi * 16 + (lane & 15);
                int cb = ks + ((lane >> 4) << 4);
                uint32_t addr = sptr(As + rr * SROW + cb);
                asm volatile(
                    "ldmatrix.sync.aligned.m8n8.x4.shared.b16 {%0,%1,%2,%3}, [%4];\n"
                    : "=r"(af[mi][0]), "=r"(af[mi][1]), "=r"(af[mi][2]), "=r"(af[mi][3])
                    : "r"(addr));
            }
            uint32_t bf[4][2];
#pragma unroll
            for (int j = 0; j < 2; j++) {
                int n_off = j * 16 + ((lane >> 4) << 3) + (lane & 7);
                int cb = ks + (((lane >> 3) & 1) << 4);
                uint32_t addr = sptr(Bs + (wn * 32 + n_off) * SROW + cb);
                asm volatile(
                    "ldmatrix.sync.aligned.m8n8.x4.shared.b16 {%0,%1,%2,%3}, [%4];\n"
                    : "=r"(bf[2 * j][0]), "=r"(bf[2 * j][1]),
                      "=r"(bf[2 * j + 1][0]), "=r"(bf[2 * j + 1][1])
                    : "r"(addr));
            }
#pragma unroll
            for (int mi = 0; mi < 2; mi++)
#pragma unroll
                for (int ni = 0; ni < 4; ni++)
                    asm volatile(
                        "mma.sync.aligned.m16n8k32.row.col.s32.s8.s8.s32 "
                        "{%0,%1,%2,%3}, {%4,%5,%6,%7}, {%8,%9}, {%0,%1,%2,%3};\n"
                        : "+r"(acc[mi][ni][0]), "+r"(acc[mi][ni][1]),
                          "+r"(acc[mi][ni][2]), "+r"(acc[mi][ni][3])
                        : "r"(af[mi][0]), "r"(af[mi][1]), "r"(af[mi][2]), "r"(af[mi][3]),
                          "r"(bf[ni][0]), "r"(bf[ni][1]));
        }
    };

    load_tile(0, 0);
    load_tile(1, 1);
    load_tile(2, 2);

    for (int kt = 0; kt < NKT; ++kt) {
        asm volatile("cp.async.wait_group 2;\n");
        __syncthreads();
        int nxt = kt + 3;
        if (nxt < NKT) load_tile(nxt, nxt & 3);
        else asm volatile("cp.async.commit_group;\n");
        if (kt < 60) compute(kt & 3, acc11);
        else         compute(kt & 3, accX);
    }

    // epilogue: out = sA*sB*(16384*acc11 + 128*accX) + bias  (+relu)
    const int g = lane >> 2, t4 = lane & 3;
#pragma unroll
    for (int mi = 0; mi < 2; mi++) {
        int r0 = m_base + wm * 32 + mi * 16 + g;
        int r1 = r0 + 8;
        float sa0 = (r0 < N_NODES) ? g_sA[r0] : 0.f;
        float sa1 = (r1 < N_NODES) ? g_sA[r1] : 0.f;
#pragma unroll
        for (int ni = 0; ni < 4; ni++) {
            int col = n_base + wn * 32 + ni * 8 + 2 * t4;
            float sb0 = g_sB[col], sb1 = g_sB[col + 1];
            float b0 = bias[col], b1 = bias[col + 1];
            float v0 = sa0 * sb0 * (16384.f * (float)acc11[mi][ni][0] + 128.f * (float)accX[mi][ni][0]) + b0;
            float v1 = sa0 * sb1 * (16384.f * (float)acc11[mi][ni][1] + 128.f * (float)accX[mi][ni][1]) + b1;
            float v2 = sa1 * sb0 * (16384.f * (float)acc11[mi][ni][2] + 128.f * (float)accX[mi][ni][2]) + b0;
            float v3 = sa1 * sb1 * (16384.f * (float)acc11[mi][ni][3] + 128.f * (float)accX[mi][ni][3]) + b1;
            if (relu) {
                v0 = fmaxf(v0, 0.f); v1 = fmaxf(v1, 0.f);
                v2 = fmaxf(v2, 0.f); v3 = fmaxf(v3, 0.f);
            }
            if (r0 < N_NODES)
                *reinterpret_cast<float2*>(C + (size_t)r0 * DIM + col) = make_float2(v0, v1);
            if (r1 < N_NODES)
                *reinterpret_cast<float2*>(C + (size_t)r1 * DIM + col) = make_float2(v2, v3);
        }
    }
}

// ---------------- launch ------------------------------------------------------
extern "C" void kernel_launch(void* const* d_in, const int* in_sizes, int n_in,
                              void* d_out, int out_size) {
    const float* entity = (const float*)d_in[0];
    const int* ei = (const int*)d_in[1];
    const int* et = (const int*)d_in[2];
    const float* Ws[3]    = {(const float*)d_in[3], (const float*)d_in[6], (const float*)d_in[9]};
    const float* roots[3] = {(const float*)d_in[4], (const float*)d_in[7], (const float*)d_in[10]};
    const float* bs[3]    = {(const float*)d_in[5], (const float*)d_in[8], (const float*)d_in[11]};
    (void)in_sizes; (void)n_in; (void)out_size;

    cudaFuncSetAttribute(k_gemm, cudaFuncAttributeMaxDynamicSharedMemorySize, SMEM_DYN);

    k_prep<<<1, 1024>>>(ei, et);
    k_place<<<(N_EDGES + 255) / 256, 256>>>(ei, et);

    dim3 ggrid(DIM / BN, (N_NODES + BM - 1) / BM);     // (6, 157)
    int xsel[3]   = {2, 0, 1};
    int outsel[3] = {0, 1, 2};
    for (int L = 0; L < 3; ++L) {
        k_aggconv<<<N_NODES + DIM, 256>>>(entity, xsel[L], roots[L], Ws[L]);
        k_gemm<<<ggrid, NTHR, SMEM_DYN>>>(bs[L], (float*)d_out, outsel[L],
                                          L < 2 ? 1 : 0);
    }
}